// round 11
// baseline (speedup 1.0000x reference)
#include <cuda_runtime.h>
#include <cuda_fp16.h>
#include <cstdint>

#define Bv 4
#define Nv 4096
#define Cv 192
#define CIN 195
#define NSTEP 13
#define WSTRIDE 432                   // 108 words = 12 mod 32 -> conflict-free LDSM
#define W_BYTES (192 * WSTRIDE)       // 82944
#define H_BYTES (128 * WSTRIDE)       // 55296
#define SM_WH 0
#define SM_HH W_BYTES
#define SM_HL (W_BYTES + H_BYTES)
#define SM_STAGE (W_BYTES + 2 * H_BYTES)          // 193536
#define SM_SNC (SM_STAGE + 4 * Cv * 4)            // 196608
#define SMEM_TOTAL (SM_SNC + 4 * 200 * 4)         // 199808
#define NTILES (Bv * Nv / 4)          // 4096 tiles of 128 points (4 n each)
#define GRID_MAIN 152
#define TPB 512
#define ROWF 584                      // floats per table row (2336 B)

// ---------------- device scratch ----------------
__device__ float g_xt[Bv * Nv * Cv];              // (x+1), [b][n][c]
__device__ float g_tab[Bv * Nv * ROWF];           // per-point: A1[192] A2[192] S[96] C[96] p[3]
__device__ __half g_wh[192 * (WSTRIDE / 2)];      // fp16 BN-folded W
__device__ float g_bias[Cv];

// ---------------- PTX helpers ----------------
__device__ __forceinline__ unsigned smem_u32(const void* p) {
    unsigned a;
    asm("{ .reg .u64 t; cvta.to.shared.u64 t, %1; cvt.u32.u64 %0, t; }" : "=r"(a) : "l"(p));
    return a;
}
#define LDSM4(r, a) \
    asm volatile("ldmatrix.sync.aligned.m8n8.x4.shared.b16 {%0,%1,%2,%3}, [%4];" \
        : "=r"((r)[0]), "=r"((r)[1]), "=r"((r)[2]), "=r"((r)[3]) : "r"(a))
#define MMA(d, a, b0, b1) \
    asm volatile("mma.sync.aligned.m16n8k16.row.col.f32.f16.f16.f32 " \
        "{%0,%1,%2,%3},{%4,%5,%6,%7},{%8,%9},{%0,%1,%2,%3};" \
        : "+f"((d)[0]), "+f"((d)[1]), "+f"((d)[2]), "+f"((d)[3]) \
        : "r"((a)[0]), "r"((a)[1]), "r"((a)[2]), "r"((a)[3]), "r"(b0), "r"(b1))

// ---------------------------------------------------------------------------
// Kernel 1: transpose x [B,C,N] -> xt [B,N,C], fused +1
// ---------------------------------------------------------------------------
__global__ void transpose_add1(const float* __restrict__ x) {
    __shared__ float tile[32][33];
    int n0 = blockIdx.x * 32, c0 = blockIdx.y * 32, b = blockIdx.z;
    int tx = threadIdx.x, ty = threadIdx.y;
#pragma unroll
    for (int i = 0; i < 4; i++)
        tile[ty + i * 8][tx] = x[((size_t)b * Cv + c0 + ty + i * 8) * Nv + n0 + tx];
    __syncthreads();
#pragma unroll
    for (int i = 0; i < 4; i++)
        g_xt[((size_t)b * Nv + n0 + ty + i * 8) * Cv + c0 + tx] = tile[tx][ty + i * 8] + 1.0f;
}

// ---------------------------------------------------------------------------
// Kernel 2: per-point table
// ---------------------------------------------------------------------------
__global__ void table_pre(const float* __restrict__ p) {
    int t = blockIdx.x * blockDim.x + threadIdx.x;
    if (t >= Bv * Nv * 32) return;
    int f = t & 31, pt = t >> 5;
    float m = (float)exp2(-(double)f * (8.9657842846620870436 / 32.0));
    float* row = g_tab + (size_t)pt * ROWF;
    const float* xr = g_xt + (size_t)pt * Cv;
#pragma unroll
    for (int d = 0; d < 3; d++) {
        float s, c;
        sincosf(50.0f * p[pt * 3 + d] * m, &s, &c);
        int c1 = d * 64 + f, c2 = c1 + 32, i96 = d * 32 + f;
        float g1 = xr[c1], g2 = xr[c2];
        row[c1] = s * g1;        row[c2] = s * g2;        // A1
        row[192 + c1] = c * g1;  row[192 + c2] = c * g2;  // A2
        row[384 + i96] = s;      row[480 + i96] = c;      // raw S, C
    }
    if (f < 3) row[576 + f] = p[pt * 3 + f];
    if (f == 3) { row[579] = 0.f; row[580] = 0.f; row[581] = 0.f; row[582] = 0.f; row[583] = 0.f; }
}

// ---------------------------------------------------------------------------
// Kernel 3: fold BN into W (fp16); channel order: pe 0..191, dp 192..194, pad 0
// ---------------------------------------------------------------------------
__global__ void prep_w(const float* __restrict__ W, const float* __restrict__ gamma,
                       const float* __restrict__ beta, const float* __restrict__ rmean,
                       const float* __restrict__ rvar) {
    int t = blockIdx.x * blockDim.x + threadIdx.x;
    if (t < Cv) {
        float inv = gamma[t] * rsqrtf(rvar[t] + 1e-5f);
        g_bias[t] = beta[t] - rmean[t] * inv;
    }
    if (t >= 192 * (WSTRIDE / 2)) return;
    int o = t / (WSTRIDE / 2), c = t % (WSTRIDE / 2);
    float w = 0.f;
    if (c < CIN) {
        int cold = (c < Cv) ? (c + 3) : (c - Cv);
        w = W[o * CIN + cold] * gamma[o] * rsqrtf(rvar[o] + 1e-5f);
    }
    g_wh[t] = __float2half_rn(w);
}

// ---------------------------------------------------------------------------
// Kernel 4: persistent main. tile = 128 points (4 n x 32 neighbors).
// 512 threads, warp grid 4(M) x 4(N): warp tile 32 rows x 48 cols.
// Build: 4 threads/point, lane-contiguous 64B loads.
// ---------------------------------------------------------------------------
__global__ void __launch_bounds__(TPB, 1) local_agg_mma(
    const float* __restrict__ p, const int* __restrict__ idx,
    float* __restrict__ out)
{
    extern __shared__ char sm[];
    const unsigned sb = smem_u32(sm);
    const int t = threadIdx.x;
    const int lane = t & 31, wid = t >> 5;
    const int wm = wid >> 2, wn = wid & 3;

    // load W plane + zero-pad H channels 196..207 (bytes 392..415) on both planes
    // NOTE: +392 is only 8-byte aligned -> uint2 stores.
    {
        const uint4* s1 = (const uint4*)g_wh;
        uint4* d1 = (uint4*)(sm + SM_WH);
#pragma unroll 4
        for (int i = t; i < W_BYTES / 16; i += TPB) d1[i] = s1[i];
        if (t < 256) {
            int plane = t >> 7, r = t & 127;
            char* a = sm + (plane ? SM_HL : SM_HH) + r * WSTRIDE + 392;
            *(uint2*)(a) = make_uint2(0u, 0u);
            *(uint2*)(a + 8) = make_uint2(0u, 0u);
            *(uint2*)(a + 16) = make_uint2(0u, 0u);
        }
    }
    __syncthreads();

    const unsigned lrow = (unsigned)(lane & 15) * WSTRIDE + ((unsigned)(lane >> 4) << 4);
    const unsigned hAH = sb + SM_HH + (unsigned)wm * 32 * WSTRIDE + lrow;
    const unsigned hAL = sb + SM_HL + (unsigned)wm * 32 * WSTRIDE + lrow;
    const unsigned bWH = sb + SM_WH + (unsigned)wn * 48 * WSTRIDE + lrow;
    float* stage = (float*)(sm + SM_STAGE);
    float* snc = (float*)(sm + SM_SNC);       // [4][200]: S[96] C[96] pn[3]

    const int pl = t >> 2;                    // point within tile (0..127)
    const int sg = t & 3;                     // channel segment

#pragma unroll 1
    for (int tile = blockIdx.x; tile < NTILES; tile += GRID_MAIN) {
        const int b0 = tile >> 10;
        const int n0 = (tile * 4) & (Nv - 1);

        // ---- stage the 4 center points' S/C/p (strided: 832 items, 512 thr) ----
        for (int i = t; i < 4 * 208; i += TPB) {
            const int nn = i / 208, ii = i % 208;
            if (ii < 195) {
                const float* rown = g_tab + (size_t)(b0 * Nv + n0 + nn) * ROWF;
                snc[nn * 200 + ii] = __ldg(rown + 384 + ii);
            }
        }
        __syncthreads();

        // ---- build H hi+lo (contiguous 64B/point loads, pure FMA) ----
        {
            const int flat = tile * 128 + pl;
            const int j = __ldg(idx + flat);
            const float* rowj = g_tab + (size_t)(b0 * Nv + j) * ROWF;
            const int nn = pl >> 5;
            const float* S = snc + nn * 200;
            const float* C = S + 96;
            const unsigned hdst = sb + SM_HH + (unsigned)pl * WSTRIDE + (unsigned)sg * 8;
            const unsigned ldst = sb + SM_HL + (unsigned)pl * WSTRIDE + (unsigned)sg * 8;
#pragma unroll
            for (int ch = 0; ch < 12; ch++) {
                const int c = ch * 16 + sg * 4;      // lanes contiguous: 4 lanes cover 64B
                float4 a1 = *(const float4*)(rowj + c);
                float4 a2 = *(const float4*)(rowj + 192 + c);
                const int d = c >> 6, e = c & 63, f0 = e & 31;
                float4 sn = *(const float4*)(S + d * 32 + f0);
                float4 cn = *(const float4*)(C + d * 32 + f0);
                float v0, v1, v2, v3;
                if (e < 32) {      // sin(uj-un)*g
                    v0 = a1.x * cn.x - a2.x * sn.x;
                    v1 = a1.y * cn.y - a2.y * sn.y;
                    v2 = a1.z * cn.z - a2.z * sn.z;
                    v3 = a1.w * cn.w - a2.w * sn.w;
                } else {           // cos(uj-un)*g
                    v0 = a2.x * cn.x + a1.x * sn.x;
                    v1 = a2.y * cn.y + a1.y * sn.y;
                    v2 = a2.z * cn.z + a1.z * sn.z;
                    v3 = a2.w * cn.w + a1.w * sn.w;
                }
                __half2 h0 = __float22half2_rn(make_float2(v0, v1));
                __half2 h1 = __float22half2_rn(make_float2(v2, v3));
                __half2 l0 = __float22half2_rn(make_float2(v0 - __half2float(__low2half(h0)),
                                                           v1 - __half2float(__high2half(h0))));
                __half2 l1 = __float22half2_rn(make_float2(v2 - __half2float(__low2half(h1)),
                                                           v3 - __half2float(__high2half(h1))));
                asm volatile("st.shared.v2.b32 [%0], {%1,%2};"
                    :: "r"(hdst + ch * 32), "r"(*(unsigned*)&h0), "r"(*(unsigned*)&h1));
                asm volatile("st.shared.v2.b32 [%0], {%1,%2};"
                    :: "r"(ldst + ch * 32), "r"(*(unsigned*)&l0), "r"(*(unsigned*)&l1));
            }
            if (sg == 0) {         // dp channels 192..195(pad)
                float4 pj4 = *(const float4*)(rowj + 576);
                const float* PN = S + 192;
                float v0 = pj4.x - PN[0], v1 = pj4.y - PN[1], v2 = pj4.z - PN[2];
                __half2 h0 = __float22half2_rn(make_float2(v0, v1));
                __half2 h1 = __float22half2_rn(make_float2(v2, 0.f));
                __half2 l0 = __float22half2_rn(make_float2(v0 - __half2float(__low2half(h0)),
                                                           v1 - __half2float(__high2half(h0))));
                __half2 l1 = __float22half2_rn(make_float2(v2 - __half2float(__low2half(h1)), 0.f));
                unsigned hd2 = sb + SM_HH + (unsigned)pl * WSTRIDE + 384;
                unsigned ld2 = sb + SM_HL + (unsigned)pl * WSTRIDE + 384;
                asm volatile("st.shared.v2.b32 [%0], {%1,%2};"
                    :: "r"(hd2), "r"(*(unsigned*)&h0), "r"(*(unsigned*)&h1));
                asm volatile("st.shared.v2.b32 [%0], {%1,%2};"
                    :: "r"(ld2), "r"(*(unsigned*)&l0), "r"(*(unsigned*)&l1));
            }
        }
        __syncthreads();

        // ---- pipelined k-loop: (Ah + Al) x W, W/AH double-buffered, AL in-step ----
        float acc[12][4];
#pragma unroll
        for (int i = 0; i < 12; i++)
#pragma unroll
            for (int r = 0; r < 4; r++) acc[i][r] = 0.f;

        unsigned AH[2][2][4], AL[2][4], WF[2][3][4];
#pragma unroll
        for (int mf = 0; mf < 2; mf++) LDSM4(AH[0][mf], hAH + mf * 16 * WSTRIDE);
#pragma unroll
        for (int q = 0; q < 3; q++) LDSM4(WF[0][q], bWH + q * 16 * WSTRIDE);

#pragma unroll
        for (int s = 0; s < NSTEP; s++) {
            const int cur = s & 1, nxt = cur ^ 1;
            const unsigned ks = (unsigned)s * 32;
            if (s + 1 < NSTEP) {
#pragma unroll
                for (int mf = 0; mf < 2; mf++) LDSM4(AH[nxt][mf], hAH + mf * 16 * WSTRIDE + ks + 32);
#pragma unroll
                for (int q = 0; q < 3; q++) LDSM4(WF[nxt][q], bWH + q * 16 * WSTRIDE + ks + 32);
            }
#pragma unroll
            for (int mf = 0; mf < 2; mf++)
#pragma unroll
                for (int q = 0; q < 3; q++) {
                    MMA(acc[mf * 6 + 2 * q],     AH[cur][mf], WF[cur][q][0], WF[cur][q][2]);
                    MMA(acc[mf * 6 + 2 * q + 1], AH[cur][mf], WF[cur][q][1], WF[cur][q][3]);
                }
#pragma unroll
            for (int mf = 0; mf < 2; mf++) LDSM4(AL[mf], hAL + mf * 16 * WSTRIDE + ks);
#pragma unroll
            for (int mf = 0; mf < 2; mf++)
#pragma unroll
                for (int q = 0; q < 3; q++) {
                    MMA(acc[mf * 6 + 2 * q],     AL[mf], WF[cur][q][0], WF[cur][q][2]);
                    MMA(acc[mf * 6 + 2 * q + 1], AL[mf], WF[cur][q][1], WF[cur][q][3]);
                }
        }

        // ---- epilogue: max over warp's 32 rows (one n), stage ----
#pragma unroll
        for (int nf = 0; nf < 6; nf++) {
            float v0 = fmaxf(fmaxf(acc[nf][0], acc[nf][2]), fmaxf(acc[6 + nf][0], acc[6 + nf][2]));
            float v1 = fmaxf(fmaxf(acc[nf][1], acc[nf][3]), fmaxf(acc[6 + nf][1], acc[6 + nf][3]));
#pragma unroll
            for (int off = 4; off < 32; off <<= 1) {
                v0 = fmaxf(v0, __shfl_xor_sync(0xffffffffu, v0, off));
                v1 = fmaxf(v1, __shfl_xor_sync(0xffffffffu, v1, off));
            }
            if (lane < 4)
                *(float2*)(stage + wm * Cv + wn * 48 + nf * 8 + 2 * lane) = make_float2(v0, v1);
        }
        __syncthreads();

        if (t < Cv) {
            const float bias = __ldg(g_bias + t);
            float4 o4;
            o4.x = fmaxf(stage[0 * Cv + t] + bias, 0.f);
            o4.y = fmaxf(stage[1 * Cv + t] + bias, 0.f);
            o4.z = fmaxf(stage[2 * Cv + t] + bias, 0.f);
            o4.w = fmaxf(stage[3 * Cv + t] + bias, 0.f);
            *(float4*)(out + ((size_t)(b0 * Cv + t)) * Nv + n0) = o4;
        }
        __syncthreads();
    }
}

// ---------------------------------------------------------------------------
extern "C" void kernel_launch(void* const* d_in, const int* in_sizes, int n_in,
                              void* d_out, int out_size) {
    const float* p     = (const float*)d_in[0];
    const float* x     = (const float*)d_in[1];
    const int*   idx   = (const int*)d_in[2];
    const float* W     = (const float*)d_in[3];
    const float* gamma = (const float*)d_in[4];
    const float* beta  = (const float*)d_in[5];
    const float* rmean = (const float*)d_in[6];
    const float* rvar  = (const float*)d_in[7];
    float* out = (float*)d_out;

    cudaFuncSetAttribute(local_agg_mma, cudaFuncAttributeMaxDynamicSharedMemorySize, SMEM_TOTAL);

    dim3 tb(32, 8);
    dim3 tg(Nv / 32, Cv / 32, Bv);
    transpose_add1<<<tg, tb>>>(x);
    table_pre<<<(Bv * Nv * 32 + 255) / 256, 256>>>(p);
    prep_w<<<(192 * (WSTRIDE / 2) + 255) / 256, 256>>>(W, gamma, beta, rmean, rvar);
    local_agg_mma<<<GRID_MAIN, TPB, SMEM_TOTAL>>>(p, idx, out);
}

// round 12
// speedup vs baseline: 1.0061x; 1.0061x over previous
#include <cuda_runtime.h>
#include <cuda_fp16.h>
#include <cstdint>

#define Bv 4
#define Nv 4096
#define Cv 192
#define CIN 195
#define NSTEP 13
#define WSTRIDE 432                   // 108 words = 12 mod 32 -> conflict-free LDSM
#define W_BYTES (192 * WSTRIDE)       // 82944
#define H_BYTES (128 * WSTRIDE)       // 55296
#define SM_WH 0
#define SM_HH W_BYTES
#define SM_HL (W_BYTES + H_BYTES)
#define SM_STAGE (W_BYTES + 2 * H_BYTES)          // 193536
#define SM_SNC (SM_STAGE + 4 * Cv * 4)            // 196608
#define SMEM_TOTAL (SM_SNC + 4 * 200 * 4)         // 199808
#define NTILES (Bv * Nv / 4)          // 4096 tiles of 128 points (4 n each)
#define GRID_MAIN 152
#define TPB 512
#define ROWF 584                      // floats per table row (2336 B)

// ---------------- device scratch ----------------
__device__ float g_xt[Bv * Nv * Cv];              // (x+1), [b][n][c]
__device__ float g_tab[Bv * Nv * ROWF];           // per-point: A1[192] A2[192] S[96] C[96] p[3]
__device__ __half g_wh[192 * (WSTRIDE / 2)];      // fp16 BN-folded W
__device__ float g_bias[Cv];

// ---------------- PTX helpers ----------------
__device__ __forceinline__ unsigned smem_u32(const void* p) {
    unsigned a;
    asm("{ .reg .u64 t; cvta.to.shared.u64 t, %1; cvt.u32.u64 %0, t; }" : "=r"(a) : "l"(p));
    return a;
}
#define LDSM4(r, a) \
    asm volatile("ldmatrix.sync.aligned.m8n8.x4.shared.b16 {%0,%1,%2,%3}, [%4];" \
        : "=r"((r)[0]), "=r"((r)[1]), "=r"((r)[2]), "=r"((r)[3]) : "r"(a))
#define MMA(d, a, b0, b1) \
    asm volatile("mma.sync.aligned.m16n8k16.row.col.f32.f16.f16.f32 " \
        "{%0,%1,%2,%3},{%4,%5,%6,%7},{%8,%9},{%0,%1,%2,%3};" \
        : "+f"((d)[0]), "+f"((d)[1]), "+f"((d)[2]), "+f"((d)[3]) \
        : "r"((a)[0]), "r"((a)[1]), "r"((a)[2]), "r"((a)[3]), "r"(b0), "r"(b1))

// ---------------------------------------------------------------------------
// Kernel 1: transpose x [B,C,N] -> xt [B,N,C], fused +1
// ---------------------------------------------------------------------------
__global__ void transpose_add1(const float* __restrict__ x) {
    __shared__ float tile[32][33];
    int n0 = blockIdx.x * 32, c0 = blockIdx.y * 32, b = blockIdx.z;
    int tx = threadIdx.x, ty = threadIdx.y;
#pragma unroll
    for (int i = 0; i < 4; i++)
        tile[ty + i * 8][tx] = x[((size_t)b * Cv + c0 + ty + i * 8) * Nv + n0 + tx];
    __syncthreads();
#pragma unroll
    for (int i = 0; i < 4; i++)
        g_xt[((size_t)b * Nv + n0 + ty + i * 8) * Cv + c0 + tx] = tile[tx][ty + i * 8] + 1.0f;
}

// ---------------------------------------------------------------------------
// Kernel 2: per-point table
// ---------------------------------------------------------------------------
__global__ void table_pre(const float* __restrict__ p) {
    int t = blockIdx.x * blockDim.x + threadIdx.x;
    if (t >= Bv * Nv * 32) return;
    int f = t & 31, pt = t >> 5;
    float m = (float)exp2(-(double)f * (8.9657842846620870436 / 32.0));
    float* row = g_tab + (size_t)pt * ROWF;
    const float* xr = g_xt + (size_t)pt * Cv;
#pragma unroll
    for (int d = 0; d < 3; d++) {
        float s, c;
        sincosf(50.0f * p[pt * 3 + d] * m, &s, &c);
        int c1 = d * 64 + f, c2 = c1 + 32, i96 = d * 32 + f;
        float g1 = xr[c1], g2 = xr[c2];
        row[c1] = s * g1;        row[c2] = s * g2;        // A1
        row[192 + c1] = c * g1;  row[192 + c2] = c * g2;  // A2
        row[384 + i96] = s;      row[480 + i96] = c;      // raw S, C
    }
    if (f < 3) row[576 + f] = p[pt * 3 + f];
    if (f == 3) { row[579] = 0.f; row[580] = 0.f; row[581] = 0.f; row[582] = 0.f; row[583] = 0.f; }
}

// ---------------------------------------------------------------------------
// Kernel 3: fold BN into W (fp16); channel order: pe 0..191, dp 192..194, pad 0
// ---------------------------------------------------------------------------
__global__ void prep_w(const float* __restrict__ W, const float* __restrict__ gamma,
                       const float* __restrict__ beta, const float* __restrict__ rmean,
                       const float* __restrict__ rvar) {
    int t = blockIdx.x * blockDim.x + threadIdx.x;
    if (t < Cv) {
        float inv = gamma[t] * rsqrtf(rvar[t] + 1e-5f);
        g_bias[t] = beta[t] - rmean[t] * inv;
    }
    if (t >= 192 * (WSTRIDE / 2)) return;
    int o = t / (WSTRIDE / 2), c = t % (WSTRIDE / 2);
    float w = 0.f;
    if (c < CIN) {
        int cold = (c < Cv) ? (c + 3) : (c - Cv);
        w = W[o * CIN + cold] * gamma[o] * rsqrtf(rvar[o] + 1e-5f);
    }
    g_wh[t] = __float2half_rn(w);
}

// ---------------------------------------------------------------------------
// Kernel 4: persistent main. tile = 128 points (4 n x 32 neighbors).
// 512 threads, warp grid 4(M) x 4(N): warp tile 32 rows x 48 cols.
// Build: 4 threads/point, lane-contiguous 64B loads.
// ---------------------------------------------------------------------------
__global__ void __launch_bounds__(TPB, 1) local_agg_mma(
    const float* __restrict__ p, const int* __restrict__ idx,
    float* __restrict__ out)
{
    extern __shared__ char sm[];
    const unsigned sb = smem_u32(sm);
    const int t = threadIdx.x;
    const int lane = t & 31, wid = t >> 5;
    const int wm = wid >> 2, wn = wid & 3;

    // load W plane + zero-pad H channels 196..207 (bytes 392..415) on both planes
    // NOTE: +392 is only 8-byte aligned -> uint2 stores.
    {
        const uint4* s1 = (const uint4*)g_wh;
        uint4* d1 = (uint4*)(sm + SM_WH);
#pragma unroll 4
        for (int i = t; i < W_BYTES / 16; i += TPB) d1[i] = s1[i];
        if (t < 256) {
            int plane = t >> 7, r = t & 127;
            char* a = sm + (plane ? SM_HL : SM_HH) + r * WSTRIDE + 392;
            *(uint2*)(a) = make_uint2(0u, 0u);
            *(uint2*)(a + 8) = make_uint2(0u, 0u);
            *(uint2*)(a + 16) = make_uint2(0u, 0u);
        }
    }
    __syncthreads();

    const unsigned lrow = (unsigned)(lane & 15) * WSTRIDE + ((unsigned)(lane >> 4) << 4);
    const unsigned hAH = sb + SM_HH + (unsigned)wm * 32 * WSTRIDE + lrow;
    const unsigned hAL = sb + SM_HL + (unsigned)wm * 32 * WSTRIDE + lrow;
    const unsigned bWH = sb + SM_WH + (unsigned)wn * 48 * WSTRIDE + lrow;
    float* stage = (float*)(sm + SM_STAGE);
    float* snc = (float*)(sm + SM_SNC);       // [4][200]: S[96] C[96] pn[3]

    const int pl = t >> 2;                    // point within tile (0..127)
    const int sg = t & 3;                     // channel segment

#pragma unroll 1
    for (int tile = blockIdx.x; tile < NTILES; tile += GRID_MAIN) {
        const int b0 = tile >> 10;
        const int n0 = (tile * 4) & (Nv - 1);

        // ---- stage the 4 center points' S/C/p (strided: 832 items, 512 thr) ----
        for (int i = t; i < 4 * 208; i += TPB) {
            const int nn = i / 208, ii = i % 208;
            if (ii < 195) {
                const float* rown = g_tab + (size_t)(b0 * Nv + n0 + nn) * ROWF;
                snc[nn * 200 + ii] = __ldg(rown + 384 + ii);
            }
        }
        __syncthreads();

        // ---- build H hi+lo (contiguous 64B/point loads, pure FMA) ----
        {
            const int flat = tile * 128 + pl;
            const int j = __ldg(idx + flat);
            const float* rowj = g_tab + (size_t)(b0 * Nv + j) * ROWF;
            const int nn = pl >> 5;
            const float* S = snc + nn * 200;
            const float* C = S + 96;
            const unsigned hdst = sb + SM_HH + (unsigned)pl * WSTRIDE + (unsigned)sg * 8;
            const unsigned ldst = sb + SM_HL + (unsigned)pl * WSTRIDE + (unsigned)sg * 8;
#pragma unroll
            for (int ch = 0; ch < 12; ch++) {
                const int c = ch * 16 + sg * 4;      // lanes contiguous: 4 lanes cover 64B
                float4 a1 = *(const float4*)(rowj + c);
                float4 a2 = *(const float4*)(rowj + 192 + c);
                const int d = c >> 6, e = c & 63, f0 = e & 31;
                float4 sn = *(const float4*)(S + d * 32 + f0);
                float4 cn = *(const float4*)(C + d * 32 + f0);
                float v0, v1, v2, v3;
                if (e < 32) {      // sin(uj-un)*g
                    v0 = a1.x * cn.x - a2.x * sn.x;
                    v1 = a1.y * cn.y - a2.y * sn.y;
                    v2 = a1.z * cn.z - a2.z * sn.z;
                    v3 = a1.w * cn.w - a2.w * sn.w;
                } else {           // cos(uj-un)*g
                    v0 = a2.x * cn.x + a1.x * sn.x;
                    v1 = a2.y * cn.y + a1.y * sn.y;
                    v2 = a2.z * cn.z + a1.z * sn.z;
                    v3 = a2.w * cn.w + a1.w * sn.w;
                }
                __half2 h0 = __float22half2_rn(make_float2(v0, v1));
                __half2 h1 = __float22half2_rn(make_float2(v2, v3));
                __half2 l0 = __float22half2_rn(make_float2(v0 - __half2float(__low2half(h0)),
                                                           v1 - __half2float(__high2half(h0))));
                __half2 l1 = __float22half2_rn(make_float2(v2 - __half2float(__low2half(h1)),
                                                           v3 - __half2float(__high2half(h1))));
                asm volatile("st.shared.v2.b32 [%0], {%1,%2};"
                    :: "r"(hdst + ch * 32), "r"(*(unsigned*)&h0), "r"(*(unsigned*)&h1));
                asm volatile("st.shared.v2.b32 [%0], {%1,%2};"
                    :: "r"(ldst + ch * 32), "r"(*(unsigned*)&l0), "r"(*(unsigned*)&l1));
            }
            if (sg == 0) {         // dp channels 192..195(pad)
                float4 pj4 = *(const float4*)(rowj + 576);
                const float* PN = S + 192;
                float v0 = pj4.x - PN[0], v1 = pj4.y - PN[1], v2 = pj4.z - PN[2];
                __half2 h0 = __float22half2_rn(make_float2(v0, v1));
                __half2 h1 = __float22half2_rn(make_float2(v2, 0.f));
                __half2 l0 = __float22half2_rn(make_float2(v0 - __half2float(__low2half(h0)),
                                                           v1 - __half2float(__high2half(h0))));
                __half2 l1 = __float22half2_rn(make_float2(v2 - __half2float(__low2half(h1)), 0.f));
                unsigned hd2 = sb + SM_HH + (unsigned)pl * WSTRIDE + 384;
                unsigned ld2 = sb + SM_HL + (unsigned)pl * WSTRIDE + 384;
                asm volatile("st.shared.v2.b32 [%0], {%1,%2};"
                    :: "r"(hd2), "r"(*(unsigned*)&h0), "r"(*(unsigned*)&h1));
                asm volatile("st.shared.v2.b32 [%0], {%1,%2};"
                    :: "r"(ld2), "r"(*(unsigned*)&l0), "r"(*(unsigned*)&l1));
            }
        }
        __syncthreads();

        // ---- pipelined k-loop: (Ah + Al) x W, W/AH double-buffered, AL in-step ----
        float acc[12][4];
#pragma unroll
        for (int i = 0; i < 12; i++)
#pragma unroll
            for (int r = 0; r < 4; r++) acc[i][r] = 0.f;

        unsigned AH[2][2][4], AL[2][4], WF[2][3][4];
#pragma unroll
        for (int mf = 0; mf < 2; mf++) LDSM4(AH[0][mf], hAH + mf * 16 * WSTRIDE);
#pragma unroll
        for (int q = 0; q < 3; q++) LDSM4(WF[0][q], bWH + q * 16 * WSTRIDE);

#pragma unroll
        for (int s = 0; s < NSTEP; s++) {
            const int cur = s & 1, nxt = cur ^ 1;
            const unsigned ks = (unsigned)s * 32;
            if (s + 1 < NSTEP) {
#pragma unroll
                for (int mf = 0; mf < 2; mf++) LDSM4(AH[nxt][mf], hAH + mf * 16 * WSTRIDE + ks + 32);
#pragma unroll
                for (int q = 0; q < 3; q++) LDSM4(WF[nxt][q], bWH + q * 16 * WSTRIDE + ks + 32);
            }
#pragma unroll
            for (int mf = 0; mf < 2; mf++)
#pragma unroll
                for (int q = 0; q < 3; q++) {
                    MMA(acc[mf * 6 + 2 * q],     AH[cur][mf], WF[cur][q][0], WF[cur][q][2]);
                    MMA(acc[mf * 6 + 2 * q + 1], AH[cur][mf], WF[cur][q][1], WF[cur][q][3]);
                }
#pragma unroll
            for (int mf = 0; mf < 2; mf++) LDSM4(AL[mf], hAL + mf * 16 * WSTRIDE + ks);
#pragma unroll
            for (int mf = 0; mf < 2; mf++)
#pragma unroll
                for (int q = 0; q < 3; q++) {
                    MMA(acc[mf * 6 + 2 * q],     AL[mf], WF[cur][q][0], WF[cur][q][2]);
                    MMA(acc[mf * 6 + 2 * q + 1], AL[mf], WF[cur][q][1], WF[cur][q][3]);
                }
        }

        // ---- epilogue: max over warp's 32 rows (one n), stage ----
#pragma unroll
        for (int nf = 0; nf < 6; nf++) {
            float v0 = fmaxf(fmaxf(acc[nf][0], acc[nf][2]), fmaxf(acc[6 + nf][0], acc[6 + nf][2]));
            float v1 = fmaxf(fmaxf(acc[nf][1], acc[nf][3]), fmaxf(acc[6 + nf][1], acc[6 + nf][3]));
#pragma unroll
            for (int off = 4; off < 32; off <<= 1) {
                v0 = fmaxf(v0, __shfl_xor_sync(0xffffffffu, v0, off));
                v1 = fmaxf(v1, __shfl_xor_sync(0xffffffffu, v1, off));
            }
            if (lane < 4)
                *(float2*)(stage + wm * Cv + wn * 48 + nf * 8 + 2 * lane) = make_float2(v0, v1);
        }
        __syncthreads();

        if (t < Cv) {
            const float bias = __ldg(g_bias + t);
            float4 o4;
            o4.x = fmaxf(stage[0 * Cv + t] + bias, 0.f);
            o4.y = fmaxf(stage[1 * Cv + t] + bias, 0.f);
            o4.z = fmaxf(stage[2 * Cv + t] + bias, 0.f);
            o4.w = fmaxf(stage[3 * Cv + t] + bias, 0.f);
            *(float4*)(out + ((size_t)(b0 * Cv + t)) * Nv + n0) = o4;
        }
        __syncthreads();
    }
}

// ---------------------------------------------------------------------------
extern "C" void kernel_launch(void* const* d_in, const int* in_sizes, int n_in,
                              void* d_out, int out_size) {
    const float* p     = (const float*)d_in[0];
    const float* x     = (const float*)d_in[1];
    const int*   idx   = (const int*)d_in[2];
    const float* W     = (const float*)d_in[3];
    const float* gamma = (const float*)d_in[4];
    const float* beta  = (const float*)d_in[5];
    const float* rmean = (const float*)d_in[6];
    const float* rvar  = (const float*)d_in[7];
    float* out = (float*)d_out;

    cudaFuncSetAttribute(local_agg_mma, cudaFuncAttributeMaxDynamicSharedMemorySize, SMEM_TOTAL);

    dim3 tb(32, 8);
    dim3 tg(Nv / 32, Cv / 32, Bv);
    transpose_add1<<<tg, tb>>>(x);
    table_pre<<<(Bv * Nv * 32 + 255) / 256, 256>>>(p);
    prep_w<<<(192 * (WSTRIDE / 2) + 255) / 256, 256>>>(W, gamma, beta, rmean, rvar);
    local_agg_mma<<<GRID_MAIN, TPB, SMEM_TOTAL>>>(p, idx, out);
}

// round 13
// speedup vs baseline: 1.4810x; 1.4721x over previous
#include <cuda_runtime.h>
#include <cuda_fp16.h>
#include <cstdint>

#define Bv 4
#define Nv 4096
#define Cv 192
#define CIN 195
#define NSTEP 13
#define WSTRIDE 432                   // 108 words = 12 mod 32 -> conflict-free LDSM
#define W_BYTES (192 * WSTRIDE)       // 82944
#define H_BYTES (128 * WSTRIDE)       // 55296
#define SM_WH 0
#define SM_HH W_BYTES
#define SM_STAGE (W_BYTES + H_BYTES)              // 138240
#define SM_SNC (SM_STAGE + 4 * Cv * 4)            // 141312
#define SMEM_TOTAL (SM_SNC + 4 * 200 * 4)         // 144512
#define NTILES (Bv * Nv / 4)          // 4096 tiles of 128 points (4 n each)
#define GRID_MAIN 152
#define TPB 512
#define ROWF 584                      // floats per table row (2336 B)

// ---------------- device scratch ----------------
__device__ float g_xt[Bv * Nv * Cv];              // (x+1), [b][n][c]
__device__ float g_tab[Bv * Nv * ROWF];           // per-point: A1[192] A2[192] S[96] C[96] p[3]
__device__ __half g_wh[192 * (WSTRIDE / 2)];      // fp16 BN-folded W
__device__ float g_bias[Cv];

// ---------------- PTX helpers ----------------
__device__ __forceinline__ unsigned smem_u32(const void* p) {
    unsigned a;
    asm("{ .reg .u64 t; cvta.to.shared.u64 t, %1; cvt.u32.u64 %0, t; }" : "=r"(a) : "l"(p));
    return a;
}
#define LDSM4(r, a) \
    asm volatile("ldmatrix.sync.aligned.m8n8.x4.shared.b16 {%0,%1,%2,%3}, [%4];" \
        : "=r"((r)[0]), "=r"((r)[1]), "=r"((r)[2]), "=r"((r)[3]) : "r"(a))
#define MMA(d, a, b0, b1) \
    asm volatile("mma.sync.aligned.m16n8k16.row.col.f32.f16.f16.f32 " \
        "{%0,%1,%2,%3},{%4,%5,%6,%7},{%8,%9},{%0,%1,%2,%3};" \
        : "+f"((d)[0]), "+f"((d)[1]), "+f"((d)[2]), "+f"((d)[3]) \
        : "r"((a)[0]), "r"((a)[1]), "r"((a)[2]), "r"((a)[3]), "r"(b0), "r"(b1))

// ---------------------------------------------------------------------------
// Kernel 1: transpose x [B,C,N] -> xt [B,N,C], fused +1
// ---------------------------------------------------------------------------
__global__ void transpose_add1(const float* __restrict__ x) {
    __shared__ float tile[32][33];
    int n0 = blockIdx.x * 32, c0 = blockIdx.y * 32, b = blockIdx.z;
    int tx = threadIdx.x, ty = threadIdx.y;
#pragma unroll
    for (int i = 0; i < 4; i++)
        tile[ty + i * 8][tx] = x[((size_t)b * Cv + c0 + ty + i * 8) * Nv + n0 + tx];
    __syncthreads();
#pragma unroll
    for (int i = 0; i < 4; i++)
        g_xt[((size_t)b * Nv + n0 + ty + i * 8) * Cv + c0 + tx] = tile[tx][ty + i * 8] + 1.0f;
}

// ---------------------------------------------------------------------------
// Kernel 2: per-point table
// ---------------------------------------------------------------------------
__global__ void table_pre(const float* __restrict__ p) {
    int t = blockIdx.x * blockDim.x + threadIdx.x;
    if (t >= Bv * Nv * 32) return;
    int f = t & 31, pt = t >> 5;
    float m = (float)exp2(-(double)f * (8.9657842846620870436 / 32.0));
    float* row = g_tab + (size_t)pt * ROWF;
    const float* xr = g_xt + (size_t)pt * Cv;
#pragma unroll
    for (int d = 0; d < 3; d++) {
        float s, c;
        sincosf(50.0f * p[pt * 3 + d] * m, &s, &c);
        int c1 = d * 64 + f, c2 = c1 + 32, i96 = d * 32 + f;
        float g1 = xr[c1], g2 = xr[c2];
        row[c1] = s * g1;        row[c2] = s * g2;        // A1
        row[192 + c1] = c * g1;  row[192 + c2] = c * g2;  // A2
        row[384 + i96] = s;      row[480 + i96] = c;      // raw S, C
    }
    if (f < 3) row[576 + f] = p[pt * 3 + f];
    if (f == 3) { row[579] = 0.f; row[580] = 0.f; row[581] = 0.f; row[582] = 0.f; row[583] = 0.f; }
}

// ---------------------------------------------------------------------------
// Kernel 3: fold BN into W (fp16); channel order: pe 0..191, dp 192..194, pad 0
// ---------------------------------------------------------------------------
__global__ void prep_w(const float* __restrict__ W, const float* __restrict__ gamma,
                       const float* __restrict__ beta, const float* __restrict__ rmean,
                       const float* __restrict__ rvar) {
    int t = blockIdx.x * blockDim.x + threadIdx.x;
    if (t < Cv) {
        float inv = gamma[t] * rsqrtf(rvar[t] + 1e-5f);
        g_bias[t] = beta[t] - rmean[t] * inv;
    }
    if (t >= 192 * (WSTRIDE / 2)) return;
    int o = t / (WSTRIDE / 2), c = t % (WSTRIDE / 2);
    float w = 0.f;
    if (c < CIN) {
        int cold = (c < Cv) ? (c + 3) : (c - Cv);
        w = W[o * CIN + cold] * gamma[o] * rsqrtf(rvar[o] + 1e-5f);
    }
    g_wh[t] = __float2half_rn(w);
}

// ---------------------------------------------------------------------------
// Kernel 4: persistent main. tile = 128 points (4 n x 32 neighbors).
// 512 threads, warp grid 4(M) x 4(N). Single fp16 product Ah*Wh.
// ---------------------------------------------------------------------------
__global__ void __launch_bounds__(TPB, 1) local_agg_mma(
    const float* __restrict__ p, const int* __restrict__ idx,
    float* __restrict__ out)
{
    extern __shared__ char sm[];
    const unsigned sb = smem_u32(sm);
    const int t = threadIdx.x;
    const int lane = t & 31, wid = t >> 5;
    const int wm = wid >> 2, wn = wid & 3;

    // load W plane + zero-pad H channels 196..207 (bytes 392..415; 8B-aligned -> uint2)
    {
        const uint4* s1 = (const uint4*)g_wh;
        uint4* d1 = (uint4*)(sm + SM_WH);
#pragma unroll 4
        for (int i = t; i < W_BYTES / 16; i += TPB) d1[i] = s1[i];
        if (t < 128) {
            char* a = sm + SM_HH + t * WSTRIDE + 392;
            *(uint2*)(a) = make_uint2(0u, 0u);
            *(uint2*)(a + 8) = make_uint2(0u, 0u);
            *(uint2*)(a + 16) = make_uint2(0u, 0u);
        }
    }
    __syncthreads();

    const unsigned lrow = (unsigned)(lane & 15) * WSTRIDE + ((unsigned)(lane >> 4) << 4);
    const unsigned hAH = sb + SM_HH + (unsigned)wm * 32 * WSTRIDE + lrow;
    const unsigned bWH = sb + SM_WH + (unsigned)wn * 48 * WSTRIDE + lrow;
    float* stage = (float*)(sm + SM_STAGE);
    float* snc = (float*)(sm + SM_SNC);       // [4][200]: S[96] C[96] pn[3]

    const int pl = t >> 2;                    // point within tile (0..127)
    const int sg = t & 3;                     // channel segment

#pragma unroll 1
    for (int tile = blockIdx.x; tile < NTILES; tile += GRID_MAIN) {
        const int b0 = tile >> 10;
        const int n0 = (tile * 4) & (Nv - 1);

        // ---- stage the 4 center points' S/C/p (strided: 832 items, 512 thr) ----
        for (int i = t; i < 4 * 208; i += TPB) {
            const int nn = i / 208, ii = i % 208;
            if (ii < 195) {
                const float* rown = g_tab + (size_t)(b0 * Nv + n0 + nn) * ROWF;
                snc[nn * 200 + ii] = __ldg(rown + 384 + ii);
            }
        }
        __syncthreads();

        // ---- build H (hi plane only; contiguous 64B/point loads, pure FMA) ----
        {
            const int flat = tile * 128 + pl;
            const int j = __ldg(idx + flat);
            const float* rowj = g_tab + (size_t)(b0 * Nv + j) * ROWF;
            const int nn = pl >> 5;
            const float* S = snc + nn * 200;
            const float* C = S + 96;
            const unsigned hdst = sb + SM_HH + (unsigned)pl * WSTRIDE + (unsigned)sg * 8;
#pragma unroll
            for (int ch = 0; ch < 12; ch++) {
                const int c = ch * 16 + sg * 4;      // 4 lanes cover contiguous 64B
                float4 a1 = *(const float4*)(rowj + c);
                float4 a2 = *(const float4*)(rowj + 192 + c);
                const int d = c >> 6, e = c & 63, f0 = e & 31;
                float4 sn = *(const float4*)(S + d * 32 + f0);
                float4 cn = *(const float4*)(C + d * 32 + f0);
                float v0, v1, v2, v3;
                if (e < 32) {      // sin(uj-un)*g
                    v0 = a1.x * cn.x - a2.x * sn.x;
                    v1 = a1.y * cn.y - a2.y * sn.y;
                    v2 = a1.z * cn.z - a2.z * sn.z;
                    v3 = a1.w * cn.w - a2.w * sn.w;
                } else {           // cos(uj-un)*g
                    v0 = a2.x * cn.x + a1.x * sn.x;
                    v1 = a2.y * cn.y + a1.y * sn.y;
                    v2 = a2.z * cn.z + a1.z * sn.z;
                    v3 = a2.w * cn.w + a1.w * sn.w;
                }
                __half2 h0 = __float22half2_rn(make_float2(v0, v1));
                __half2 h1 = __float22half2_rn(make_float2(v2, v3));
                asm volatile("st.shared.v2.b32 [%0], {%1,%2};"
                    :: "r"(hdst + ch * 32), "r"(*(unsigned*)&h0), "r"(*(unsigned*)&h1));
            }
            if (sg == 0) {         // dp channels 192..195(pad)
                float4 pj4 = *(const float4*)(rowj + 576);
                const float* PN = S + 192;
                float v0 = pj4.x - PN[0], v1 = pj4.y - PN[1], v2 = pj4.z - PN[2];
                __half2 h0 = __float22half2_rn(make_float2(v0, v1));
                __half2 h1 = __float22half2_rn(make_float2(v2, 0.f));
                unsigned hd2 = sb + SM_HH + (unsigned)pl * WSTRIDE + 384;
                asm volatile("st.shared.v2.b32 [%0], {%1,%2};"
                    :: "r"(hd2), "r"(*(unsigned*)&h0), "r"(*(unsigned*)&h1));
            }
        }
        __syncthreads();

        // ---- pipelined k-loop: Ah x Wh only, double-buffered frags ----
        float acc[12][4];
#pragma unroll
        for (int i = 0; i < 12; i++)
#pragma unroll
            for (int r = 0; r < 4; r++) acc[i][r] = 0.f;

        unsigned AH[2][2][4], WF[2][3][4];
#pragma unroll
        for (int mf = 0; mf < 2; mf++) LDSM4(AH[0][mf], hAH + mf * 16 * WSTRIDE);
#pragma unroll
        for (int q = 0; q < 3; q++) LDSM4(WF[0][q], bWH + q * 16 * WSTRIDE);

#pragma unroll
        for (int s = 0; s < NSTEP; s++) {
            const int cur = s & 1, nxt = cur ^ 1;
            const unsigned ks = (unsigned)s * 32;
            if (s + 1 < NSTEP) {
#pragma unroll
                for (int mf = 0; mf < 2; mf++) LDSM4(AH[nxt][mf], hAH + mf * 16 * WSTRIDE + ks + 32);
#pragma unroll
                for (int q = 0; q < 3; q++) LDSM4(WF[nxt][q], bWH + q * 16 * WSTRIDE + ks + 32);
            }
#pragma unroll
            for (int mf = 0; mf < 2; mf++)
#pragma unroll
                for (int q = 0; q < 3; q++) {
                    MMA(acc[mf * 6 + 2 * q],     AH[cur][mf], WF[cur][q][0], WF[cur][q][2]);
                    MMA(acc[mf * 6 + 2 * q + 1], AH[cur][mf], WF[cur][q][1], WF[cur][q][3]);
                }
        }

        // ---- epilogue: max over warp's 32 rows (one n), stage ----
#pragma unroll
        for (int nf = 0; nf < 6; nf++) {
            float v0 = fmaxf(fmaxf(acc[nf][0], acc[nf][2]), fmaxf(acc[6 + nf][0], acc[6 + nf][2]));
            float v1 = fmaxf(fmaxf(acc[nf][1], acc[nf][3]), fmaxf(acc[6 + nf][1], acc[6 + nf][3]));
#pragma unroll
            for (int off = 4; off < 32; off <<= 1) {
                v0 = fmaxf(v0, __shfl_xor_sync(0xffffffffu, v0, off));
                v1 = fmaxf(v1, __shfl_xor_sync(0xffffffffu, v1, off));
            }
            if (lane < 4)
                *(float2*)(stage + wm * Cv + wn * 48 + nf * 8 + 2 * lane) = make_float2(v0, v1);
        }
        __syncthreads();

        if (t < Cv) {
            const float bias = __ldg(g_bias + t);
            float4 o4;
            o4.x = fmaxf(stage[0 * Cv + t] + bias, 0.f);
            o4.y = fmaxf(stage[1 * Cv + t] + bias, 0.f);
            o4.z = fmaxf(stage[2 * Cv + t] + bias, 0.f);
            o4.w = fmaxf(stage[3 * Cv + t] + bias, 0.f);
            *(float4*)(out + ((size_t)(b0 * Cv + t)) * Nv + n0) = o4;
        }
        __syncthreads();
    }
}

// ---------------------------------------------------------------------------
extern "C" void kernel_launch(void* const* d_in, const int* in_sizes, int n_in,
                              void* d_out, int out_size) {
    const float* p     = (const float*)d_in[0];
    const float* x     = (const float*)d_in[1];
    const int*   idx   = (const int*)d_in[2];
    const float* W     = (const float*)d_in[3];
    const float* gamma = (const float*)d_in[4];
    const float* beta  = (const float*)d_in[5];
    const float* rmean = (const float*)d_in[6];
    const float* rvar  = (const float*)d_in[7];
    float* out = (float*)d_out;

    cudaFuncSetAttribute(local_agg_mma, cudaFuncAttributeMaxDynamicSharedMemorySize, SMEM_TOTAL);

    dim3 tb(32, 8);
    dim3 tg(Nv / 32, Cv / 32, Bv);
    transpose_add1<<<tg, tb>>>(x);
    table_pre<<<(Bv * Nv * 32 + 255) / 256, 256>>>(p);
    prep_w<<<(192 * (WSTRIDE / 2) + 255) / 256, 256>>>(W, gamma, beta, rmean, rvar);
    local_agg_mma<<<GRID_MAIN, TPB, SMEM_TOTAL>>>(p, idx, out);
}

// round 14
// speedup vs baseline: 1.6411x; 1.1081x over previous
#include <cuda_runtime.h>
#include <cuda_fp16.h>
#include <cstdint>

#define Bv 4
#define Nv 4096
#define Cv 192
#define CIN 195
#define NSTEP 13
#define WSTRIDE 432                   // 108 words = 12 mod 32 -> conflict-free LDSM
#define W_BYTES (192 * WSTRIDE)       // 82944
#define H_BYTES (128 * WSTRIDE)       // 55296
#define SM_WH 0
#define SM_H0 W_BYTES
#define SM_STAGE (W_BYTES + 2 * H_BYTES)          // 193536
#define SM_SNC (SM_STAGE + 4 * Cv * 4)            // 196608
#define SMEM_TOTAL (SM_SNC + 4 * 200 * 4)         // 199808
#define NTILES (Bv * Nv / 4)          // 4096 tiles of 128 points (4 n each)
#define GRID_MAIN 152
#define TPB 512
#define ROWF 584                      // floats per table row (2336 B)

// ---------------- device scratch ----------------
__device__ float g_xt[Bv * Nv * Cv];              // (x+1), [b][n][c]
__device__ float g_tab[Bv * Nv * ROWF];           // per-point: A1[192] A2[192] S[96] C[96] p[3]
__device__ __half g_wh[192 * (WSTRIDE / 2)];      // fp16 BN-folded W
__device__ float g_bias[Cv];

// ---------------- PTX helpers ----------------
__device__ __forceinline__ unsigned smem_u32(const void* p) {
    unsigned a;
    asm("{ .reg .u64 t; cvta.to.shared.u64 t, %1; cvt.u32.u64 %0, t; }" : "=r"(a) : "l"(p));
    return a;
}
#define LDSM4(r, a) \
    asm volatile("ldmatrix.sync.aligned.m8n8.x4.shared.b16 {%0,%1,%2,%3}, [%4];" \
        : "=r"((r)[0]), "=r"((r)[1]), "=r"((r)[2]), "=r"((r)[3]) : "r"(a))
#define MMA(d, a, b0, b1) \
    asm volatile("mma.sync.aligned.m16n8k16.row.col.f32.f16.f16.f32 " \
        "{%0,%1,%2,%3},{%4,%5,%6,%7},{%8,%9},{%0,%1,%2,%3};" \
        : "+f"((d)[0]), "+f"((d)[1]), "+f"((d)[2]), "+f"((d)[3]) \
        : "r"((a)[0]), "r"((a)[1]), "r"((a)[2]), "r"((a)[3]), "r"(b0), "r"(b1))

// ---------------------------------------------------------------------------
// Kernel 1: transpose x [B,C,N] -> xt [B,N,C], fused +1
// ---------------------------------------------------------------------------
__global__ void transpose_add1(const float* __restrict__ x) {
    __shared__ float tile[32][33];
    int n0 = blockIdx.x * 32, c0 = blockIdx.y * 32, b = blockIdx.z;
    int tx = threadIdx.x, ty = threadIdx.y;
#pragma unroll
    for (int i = 0; i < 4; i++)
        tile[ty + i * 8][tx] = x[((size_t)b * Cv + c0 + ty + i * 8) * Nv + n0 + tx];
    __syncthreads();
#pragma unroll
    for (int i = 0; i < 4; i++)
        g_xt[((size_t)b * Nv + n0 + ty + i * 8) * Cv + c0 + tx] = tile[tx][ty + i * 8] + 1.0f;
}

// ---------------------------------------------------------------------------
// Kernel 2: per-point table
// ---------------------------------------------------------------------------
__global__ void table_pre(const float* __restrict__ p) {
    int t = blockIdx.x * blockDim.x + threadIdx.x;
    if (t >= Bv * Nv * 32) return;
    int f = t & 31, pt = t >> 5;
    float m = (float)exp2(-(double)f * (8.9657842846620870436 / 32.0));
    float* row = g_tab + (size_t)pt * ROWF;
    const float* xr = g_xt + (size_t)pt * Cv;
#pragma unroll
    for (int d = 0; d < 3; d++) {
        float s, c;
        sincosf(50.0f * p[pt * 3 + d] * m, &s, &c);
        int c1 = d * 64 + f, c2 = c1 + 32, i96 = d * 32 + f;
        float g1 = xr[c1], g2 = xr[c2];
        row[c1] = s * g1;        row[c2] = s * g2;        // A1
        row[192 + c1] = c * g1;  row[192 + c2] = c * g2;  // A2
        row[384 + i96] = s;      row[480 + i96] = c;      // raw S, C
    }
    if (f < 3) row[576 + f] = p[pt * 3 + f];
    if (f == 3) { row[579] = 0.f; row[580] = 0.f; row[581] = 0.f; row[582] = 0.f; row[583] = 0.f; }
}

// ---------------------------------------------------------------------------
// Kernel 3: fold BN into W (fp16); channel order: pe 0..191, dp 192..194, pad 0
// ---------------------------------------------------------------------------
__global__ void prep_w(const float* __restrict__ W, const float* __restrict__ gamma,
                       const float* __restrict__ beta, const float* __restrict__ rmean,
                       const float* __restrict__ rvar) {
    int t = blockIdx.x * blockDim.x + threadIdx.x;
    if (t < Cv) {
        float inv = gamma[t] * rsqrtf(rvar[t] + 1e-5f);
        g_bias[t] = beta[t] - rmean[t] * inv;
    }
    if (t >= 192 * (WSTRIDE / 2)) return;
    int o = t / (WSTRIDE / 2), c = t % (WSTRIDE / 2);
    float w = 0.f;
    if (c < CIN) {
        int cold = (c < Cv) ? (c + 3) : (c - Cv);
        w = W[o * CIN + cold] * gamma[o] * rsqrtf(rvar[o] + 1e-5f);
    }
    g_wh[t] = __float2half_rn(w);
}

// ---------------- build helpers ----------------
__device__ __forceinline__ void build_ch(const float* __restrict__ rowj,
                                         const float* __restrict__ S,
                                         const float* __restrict__ C,
                                         int c, unsigned dst) {
    float4 a1 = *(const float4*)(rowj + c);
    float4 a2 = *(const float4*)(rowj + 192 + c);
    const int d = c >> 6, e = c & 63, f0 = e & 31;
    float4 sn = *(const float4*)(S + d * 32 + f0);
    float4 cn = *(const float4*)(C + d * 32 + f0);
    float v0, v1, v2, v3;
    if (e < 32) {      // sin(uj-un)*g
        v0 = a1.x * cn.x - a2.x * sn.x;
        v1 = a1.y * cn.y - a2.y * sn.y;
        v2 = a1.z * cn.z - a2.z * sn.z;
        v3 = a1.w * cn.w - a2.w * sn.w;
    } else {           // cos(uj-un)*g
        v0 = a2.x * cn.x + a1.x * sn.x;
        v1 = a2.y * cn.y + a1.y * sn.y;
        v2 = a2.z * cn.z + a1.z * sn.z;
        v3 = a2.w * cn.w + a1.w * sn.w;
    }
    __half2 h0 = __float22half2_rn(make_float2(v0, v1));
    __half2 h1 = __float22half2_rn(make_float2(v2, v3));
    asm volatile("st.shared.v2.b32 [%0], {%1,%2};"
        :: "r"(dst), "r"(*(unsigned*)&h0), "r"(*(unsigned*)&h1));
}

__device__ __forceinline__ void build_dp(const float* __restrict__ rowj,
                                         const float* __restrict__ PN, unsigned dst) {
    float4 pj4 = *(const float4*)(rowj + 576);
    float v0 = pj4.x - PN[0], v1 = pj4.y - PN[1], v2 = pj4.z - PN[2];
    __half2 h0 = __float22half2_rn(make_float2(v0, v1));
    __half2 h1 = __float22half2_rn(make_float2(v2, 0.f));
    asm volatile("st.shared.v2.b32 [%0], {%1,%2};"
        :: "r"(dst), "r"(*(unsigned*)&h0), "r"(*(unsigned*)&h1));
}

// ---------------------------------------------------------------------------
// Kernel 4: persistent main, tile-level software pipeline.
// tile = 128 points (4 n x 32 nbr). 512 thr, 4(M) x 4(N) warps.
// k-loop step s of tile i also executes build-step s of tile i+GRID into the
// other H buffer -> LSU and tensor pipes overlap.
// ---------------------------------------------------------------------------
__global__ void __launch_bounds__(TPB, 1) local_agg_mma(
    const float* __restrict__ p, const int* __restrict__ idx,
    float* __restrict__ out)
{
    extern __shared__ char sm[];
    const unsigned sb = smem_u32(sm);
    const int t = threadIdx.x;
    const int lane = t & 31, wid = t >> 5;
    const int wm = wid >> 2, wn = wid & 3;

    // load W plane + zero-pad channels 196..207 on BOTH H buffers (8B-aligned -> uint2)
    {
        const uint4* s1 = (const uint4*)g_wh;
        uint4* d1 = (uint4*)(sm + SM_WH);
#pragma unroll 4
        for (int i = t; i < W_BYTES / 16; i += TPB) d1[i] = s1[i];
        if (t < 256) {
            char* a = sm + SM_H0 + (t >> 7) * H_BYTES + (t & 127) * WSTRIDE + 392;
            *(uint2*)(a) = make_uint2(0u, 0u);
            *(uint2*)(a + 8) = make_uint2(0u, 0u);
            *(uint2*)(a + 16) = make_uint2(0u, 0u);
        }
    }

    const unsigned lrow = (unsigned)(lane & 15) * WSTRIDE + ((unsigned)(lane >> 4) << 4);
    const unsigned bWH = sb + SM_WH + (unsigned)wn * 48 * WSTRIDE + lrow;
    float* stage = (float*)(sm + SM_STAGE);
    float* snc = (float*)(sm + SM_SNC);       // [4][200]: S[96] C[96] pn[3]

    const int pl = t >> 2;                    // point within tile (0..127)
    const int sg = t & 3;                     // channel segment

    // ---- prologue: stage snc + build H[0] for this CTA's first tile ----
    const int tile0 = blockIdx.x;
    {
        const int b0 = tile0 >> 10;
        const int n0 = (tile0 * 4) & (Nv - 1);
        for (int i = t; i < 4 * 208; i += TPB) {
            const int nn = i / 208, ii = i % 208;
            if (ii < 195)
                snc[nn * 200 + ii] = __ldg(g_tab + (size_t)(b0 * Nv + n0 + nn) * ROWF + 384 + ii);
        }
        __syncthreads();
        const int j = __ldg(idx + tile0 * 128 + pl);
        const float* rowj = g_tab + (size_t)(b0 * Nv + j) * ROWF;
        const float* S = snc + (pl >> 5) * 200;
        const unsigned hbase = sb + SM_H0 + (unsigned)pl * WSTRIDE;
#pragma unroll
        for (int s = 0; s < 12; s++)
            build_ch(rowj, S, S + 96, s * 16 + sg * 4, hbase + sg * 8 + s * 32);
        if (sg == 0) build_dp(rowj, S + 192, hbase + 384);
    }

#pragma unroll 1
    for (int tile = tile0, it = 0; tile < NTILES; tile += GRID_MAIN, it++) {
        const int cur = it & 1, nb = cur ^ 1;
        const int b0 = tile >> 10;
        const int n0 = (tile * 4) & (Nv - 1);
        const int ntile = tile + GRID_MAIN;
        const bool have_next = ntile < NTILES;

        // ---- stage snc for NEXT tile's centers (prev k-loop reads are sync'd off) ----
        if (have_next) {
            const int bn_ = ntile >> 10;
            const int nn0 = (ntile * 4) & (Nv - 1);
            for (int i = t; i < 4 * 208; i += TPB) {
                const int nn = i / 208, ii = i % 208;
                if (ii < 195)
                    snc[nn * 200 + ii] = __ldg(g_tab + (size_t)(bn_ * Nv + nn0 + nn) * ROWF + 384 + ii);
            }
        }
        __syncthreads();   // publish H[cur] (built last iter) + snc(next)

        // next-tile build pointers
        const float* rowjn = nullptr;
        const float* Sn = nullptr;
        unsigned hbn = 0;
        if (have_next) {
            const int bn_ = ntile >> 10;
            const int jn = __ldg(idx + ntile * 128 + pl);
            rowjn = g_tab + (size_t)(bn_ * Nv + jn) * ROWF;
            Sn = snc + (pl >> 5) * 200;
            hbn = sb + SM_H0 + (unsigned)nb * H_BYTES + (unsigned)pl * WSTRIDE;
        }

        const unsigned hAH = sb + SM_H0 + (unsigned)cur * H_BYTES
                           + (unsigned)wm * 32 * WSTRIDE + lrow;

        // ---- fused k-loop: MMA(H[cur]) + build(H[nb]) ----
        float acc[12][4];
#pragma unroll
        for (int i = 0; i < 12; i++)
#pragma unroll
            for (int r = 0; r < 4; r++) acc[i][r] = 0.f;

        unsigned AH[2][2][4], WF[2][3][4];
#pragma unroll
        for (int mf = 0; mf < 2; mf++) LDSM4(AH[0][mf], hAH + mf * 16 * WSTRIDE);
#pragma unroll
        for (int q = 0; q < 3; q++) LDSM4(WF[0][q], bWH + q * 16 * WSTRIDE);

#pragma unroll
        for (int s = 0; s < NSTEP; s++) {
            const int c2 = s & 1, nxt = c2 ^ 1;
            const unsigned ks = (unsigned)s * 32;
            if (s + 1 < NSTEP) {
#pragma unroll
                for (int mf = 0; mf < 2; mf++) LDSM4(AH[nxt][mf], hAH + mf * 16 * WSTRIDE + ks + 32);
#pragma unroll
                for (int q = 0; q < 3; q++) LDSM4(WF[nxt][q], bWH + q * 16 * WSTRIDE + ks + 32);
            }
            // build-step s of next tile (overlaps with this step's MMAs)
            if (have_next) {
                if (s < 12) build_ch(rowjn, Sn, Sn + 96, s * 16 + sg * 4, hbn + sg * 8 + s * 32);
                else if (sg == 0) build_dp(rowjn, Sn + 192, hbn + 384);
            }
#pragma unroll
            for (int mf = 0; mf < 2; mf++)
#pragma unroll
                for (int q = 0; q < 3; q++) {
                    MMA(acc[mf * 6 + 2 * q],     AH[c2][mf], WF[c2][q][0], WF[c2][q][2]);
                    MMA(acc[mf * 6 + 2 * q + 1], AH[c2][mf], WF[c2][q][1], WF[c2][q][3]);
                }
        }

        // ---- epilogue: max over warp's 32 rows (one n), stage ----
#pragma unroll
        for (int nf = 0; nf < 6; nf++) {
            float v0 = fmaxf(fmaxf(acc[nf][0], acc[nf][2]), fmaxf(acc[6 + nf][0], acc[6 + nf][2]));
            float v1 = fmaxf(fmaxf(acc[nf][1], acc[nf][3]), fmaxf(acc[6 + nf][1], acc[6 + nf][3]));
#pragma unroll
            for (int off = 4; off < 32; off <<= 1) {
                v0 = fmaxf(v0, __shfl_xor_sync(0xffffffffu, v0, off));
                v1 = fmaxf(v1, __shfl_xor_sync(0xffffffffu, v1, off));
            }
            if (lane < 4)
                *(float2*)(stage + wm * Cv + wn * 48 + nf * 8 + 2 * lane) = make_float2(v0, v1);
        }
        __syncthreads();   // publish stage; also orders k-loop snc reads before next staging

        if (t < Cv) {
            const float bias = __ldg(g_bias + t);
            float4 o4;
            o4.x = fmaxf(stage[0 * Cv + t] + bias, 0.f);
            o4.y = fmaxf(stage[1 * Cv + t] + bias, 0.f);
            o4.z = fmaxf(stage[2 * Cv + t] + bias, 0.f);
            o4.w = fmaxf(stage[3 * Cv + t] + bias, 0.f);
            *(float4*)(out + ((size_t)(b0 * Cv + t)) * Nv + n0) = o4;
        }
    }
}

// ---------------------------------------------------------------------------
extern "C" void kernel_launch(void* const* d_in, const int* in_sizes, int n_in,
                              void* d_out, int out_size) {
    const float* p     = (const float*)d_in[0];
    const float* x     = (const float*)d_in[1];
    const int*   idx   = (const int*)d_in[2];
    const float* W     = (const float*)d_in[3];
    const float* gamma = (const float*)d_in[4];
    const float* beta  = (const float*)d_in[5];
    const float* rmean = (const float*)d_in[6];
    const float* rvar  = (const float*)d_in[7];
    float* out = (float*)d_out;

    cudaFuncSetAttribute(local_agg_mma, cudaFuncAttributeMaxDynamicSharedMemorySize, SMEM_TOTAL);

    dim3 tb(32, 8);
    dim3 tg(Nv / 32, Cv / 32, Bv);
    transpose_add1<<<tg, tb>>>(x);
    table_pre<<<(Bv * Nv * 32 + 255) / 256, 256>>>(p);
    prep_w<<<(192 * (WSTRIDE / 2) + 255) / 256, 256>>>(W, gamma, beta, rmean, rvar);
    local_agg_mma<<<GRID_MAIN, TPB, SMEM_TOTAL>>>(p, idx, out);
}